// round 3
// baseline (speedup 1.0000x reference)
#include <cuda_runtime.h>

// out[i, j] = (2*x[i, j] + 3) / (i + 1), x is 8192x8192 fp32.
// HBM-bound streaming. R3: persistent single-wave grid (740 CTAs = 148 SMs x
// 5 CTAs/SM), grid-stride over 2048-vec chunks, 8x front-batched LDG.128 per
// iteration. Eliminates ~10 wave transitions + ragged final wave of R2.

static constexpr int N_ROWS = 8192;
static constexpr int N_COLS = 8192;
static constexpr long long N_ELEMS = (long long)N_ROWS * N_COLS;   // 2^26
static constexpr long long N_VEC = N_ELEMS / 4;                    // 2^24 float4s
static constexpr int THREADS = 256;
static constexpr int UNROLL = 8;
static constexpr int CHUNK = THREADS * UNROLL;                     // 2048 vecs
static constexpr long long N_CHUNKS = N_VEC / CHUNK;               // 8192, exact
static constexpr int GRID = 148 * 5;                               // 740: one wave

__global__ void __launch_bounds__(THREADS, 5)
affine_rowdiv_kernel(const float4* __restrict__ in, float4* __restrict__ out) {
    for (long long b = blockIdx.x; b < N_CHUNKS; b += gridDim.x) {
        long long base = b * CHUNK + threadIdx.x;

        // Front-batch 8 independent LDG.128 (MLP_eff ~8 per thread).
        float4 v[UNROLL];
#pragma unroll
        for (int k = 0; k < UNROLL; k++) {
            v[k] = __ldcs(&in[base + (long long)k * THREADS]);
        }

#pragma unroll
        for (int k = 0; k < UNROLL; k++) {
            long long idx = base + (long long)k * THREADS;
            // 2048 float4s per row -> row = idx >> 11
            int row = (int)(idx >> 11);
            float inv = 1.0f / (float)(row + 1);
            float4 r;
            r.x = fmaf(2.0f, v[k].x, 3.0f) * inv;
            r.y = fmaf(2.0f, v[k].y, 3.0f) * inv;
            r.z = fmaf(2.0f, v[k].z, 3.0f) * inv;
            r.w = fmaf(2.0f, v[k].w, 3.0f) * inv;
            __stcs(&out[idx], r);
        }
    }
}

extern "C" void kernel_launch(void* const* d_in, const int* in_sizes, int n_in,
                              void* d_out, int out_size) {
    const float4* in = (const float4*)d_in[0];
    float4* out = (float4*)d_out;
    affine_rowdiv_kernel<<<GRID, THREADS>>>(in, out);
}

// round 4
// speedup vs baseline: 1.1822x; 1.1822x over previous
#include <cuda_runtime.h>

// out[i, j] = (2*x[i, j] + 3) / (i + 1), x is 8192x8192 fp32.
// HBM-bound streaming. R4: flat launch (HW wave balancing beats persistent
// grid — R3 post-mortem), UNROLL=4 to balance MLP (~4 in-flight LDG.128/thread)
// against occupancy (regs ~30 -> 8 CTAs/SM vs R2's 5).

static constexpr int N_ROWS = 8192;
static constexpr int N_COLS = 8192;
static constexpr long long N_ELEMS = (long long)N_ROWS * N_COLS;   // 2^26
static constexpr long long N_VEC = N_ELEMS / 4;                    // 2^24 float4s
static constexpr int THREADS = 256;
static constexpr int UNROLL = 4;
// 2^24 / (256*4) = 16384 blocks, exact — no tail.
static constexpr int BLOCKS = (int)(N_VEC / (THREADS * UNROLL));

__global__ void __launch_bounds__(THREADS)
affine_rowdiv_kernel(const float4* __restrict__ in, float4* __restrict__ out) {
    long long base = (long long)blockIdx.x * (THREADS * UNROLL) + threadIdx.x;

    // Front-batch 4 independent LDG.128 per thread.
    float4 v[UNROLL];
#pragma unroll
    for (int k = 0; k < UNROLL; k++) {
        v[k] = __ldcs(&in[base + (long long)k * THREADS]);
    }

#pragma unroll
    for (int k = 0; k < UNROLL; k++) {
        long long idx = base + (long long)k * THREADS;
        // 2048 float4s per row -> row = idx >> 11
        int row = (int)(idx >> 11);
        float inv = 1.0f / (float)(row + 1);
        float4 r;
        r.x = fmaf(2.0f, v[k].x, 3.0f) * inv;
        r.y = fmaf(2.0f, v[k].y, 3.0f) * inv;
        r.z = fmaf(2.0f, v[k].z, 3.0f) * inv;
        r.w = fmaf(2.0f, v[k].w, 3.0f) * inv;
        __stcs(&out[idx], r);
    }
}

extern "C" void kernel_launch(void* const* d_in, const int* in_sizes, int n_in,
                              void* d_out, int out_size) {
    const float4* in = (const float4*)d_in[0];
    float4* out = (float4*)d_out;
    affine_rowdiv_kernel<<<BLOCKS, THREADS>>>(in, out);
}